// round 3
// baseline (speedup 1.0000x reference)
#include <cuda_runtime.h>

// Problem constants (fixed by the dataset: sess_emb [16384, 256] fp32)
#define NMAX 16384
#define D    256
#define BM   64     // rows per block
#define BN   128    // keys per tile
#define BK   32     // k-chunk
#define TM   4      // rows per thread
#define TN   8      // cols per thread
#define SPAD 4
#define SSTR (BN + SPAD)   // 132: score-tile row stride (bank-conflict-free scan)

// Scratch: normalized embeddings (16 MB). Static __device__ is the allowed
// scratch mechanism (no cudaMalloc anywhere).
__device__ float g_En[NMAX * D];

// ---------------------------------------------------------------------------
// Kernel 1: row-normalize with the reference's eps convention:
//   fenmu = sqrt(sum(x^2 + 1e-6))  (eps added per element BEFORE the sum)
// ---------------------------------------------------------------------------
__global__ void norm_kernel(const float* __restrict__ E) {
    int row = blockIdx.x;
    int tid = threadIdx.x;              // 256 threads == D
    float v = E[row * D + tid];
    float s = v * v + 1e-6f;
    #pragma unroll
    for (int o = 16; o > 0; o >>= 1) s += __shfl_xor_sync(0xffffffffu, s, o);
    __shared__ float red[8];
    if ((tid & 31) == 0) red[tid >> 5] = s;
    __syncthreads();
    if (tid < 8) {
        float t = red[tid];
        #pragma unroll
        for (int o = 4; o > 0; o >>= 1) t += __shfl_xor_sync(0x000000ffu, t, o);
        if (tid == 0) red[0] = t;
    }
    __syncthreads();
    float rinv = rsqrtf(red[0]);
    g_En[row * D + tid] = v * rinv;
}

// ---------------------------------------------------------------------------
// Kernel 2: fused scores + softmax stats + top-3 + second softmax + gather.
// Scores use fixed shift 1.0 (cos < 1 guaranteed by the eps in the norm),
// so softmax value s_j = exp(x_j - 1) / Z  with Z = sum_j exp(x_j - 1).
// Softmax is monotone, so top-3 of softmax == top-3 of raw cos.
// ---------------------------------------------------------------------------
__global__ __launch_bounds__(256, 2)
void neigh_kernel(const float* __restrict__ E, float* __restrict__ out, int n) {
    extern __shared__ unsigned char smembuf[];
    float (*sQ)[BM]   = (float (*)[BM])(smembuf);                         //  8 KB
    float (*sK)[BN]   = (float (*)[BN])(smembuf + BK * BM * 4);           // 16 KB
    float (*sS)[SSTR] = (float (*)[SSTR])(smembuf + BK * BM * 4 + BK * BN * 4); // 33.8 KB

    // Merge-phase overlay inside the (then-dead) score tile region.
    float* mBase = (float*)sS;
    float (*mV)[4][3]   = (float (*)[4][3])(mBase);                 // 768 f
    int   (*mI)[4][3]   = (int   (*)[4][3])(mBase + 768);           // 768 i
    float (*mZ)[4]      = (float (*)[4])   (mBase + 1536);          // 256 f
    float (*wRow)[3]    = (float (*)[3])   (mBase + 1792);          // 192 f
    int   (*iRow)[3]    = (int   (*)[3])   (mBase + 1984);          // 192 i

    const int tid  = threadIdx.x;
    const int row0 = blockIdx.x * BM;

    // GEMM register-tile coordinates: 16x16 thread grid, 4x8 per thread.
    const int trm = (tid >> 4) * TM;    // row offset in tile
    const int tcn = (tid & 15) * TN;    // col offset in tile

    // Loader mapping
    const int qm = tid >> 2;            // 0..63   (Q row)
    const int qk = (tid & 3) * 8;       // Q k-offset, 8 elems
    const int kn = tid >> 1;            // 0..127  (K row)
    const int kk = (tid & 1) * 16;      // K k-offset, 16 elems

    // Scan mapping: 4 threads per row, interleaved cols (conflict-free with SSTR=132)
    const int srow = tid >> 2;          // 0..63
    const int sq   = tid & 3;

    float tv0 = -2.f, tv1 = -2.f, tv2 = -2.f;
    int   ti0 = 0x7fffffff, ti1 = 0x7fffffff, ti2 = 0x7fffffff;
    float Z = 0.f;

    const float* qbase = &g_En[(row0 + qm) * D + qk];
    const float* kbase = &g_En[kn * D + kk];

    const int nTiles = n / BN;
    for (int kt = 0; kt < nTiles; kt++) {
        const int col0 = kt * BN;
        const float* kb = kbase + (size_t)col0 * D;

        float acc[TM][TN];
        #pragma unroll
        for (int i = 0; i < TM; i++)
            #pragma unroll
            for (int j = 0; j < TN; j++) acc[i][j] = 0.f;

        for (int dk = 0; dk < D; dk += BK) {
            // --- stage Q (BM x BK, transposed) and K (BN x BK, transposed) ---
            float4 a0 = *(const float4*)(qbase + dk);
            float4 a1 = *(const float4*)(qbase + dk + 4);
            float4 b0 = *(const float4*)(kb + dk);
            float4 b1 = *(const float4*)(kb + dk + 4);
            float4 b2 = *(const float4*)(kb + dk + 8);
            float4 b3 = *(const float4*)(kb + dk + 12);
            sQ[qk + 0][qm] = a0.x; sQ[qk + 1][qm] = a0.y;
            sQ[qk + 2][qm] = a0.z; sQ[qk + 3][qm] = a0.w;
            sQ[qk + 4][qm] = a1.x; sQ[qk + 5][qm] = a1.y;
            sQ[qk + 6][qm] = a1.z; sQ[qk + 7][qm] = a1.w;
            sK[kk +  0][kn] = b0.x; sK[kk +  1][kn] = b0.y;
            sK[kk +  2][kn] = b0.z; sK[kk +  3][kn] = b0.w;
            sK[kk +  4][kn] = b1.x; sK[kk +  5][kn] = b1.y;
            sK[kk +  6][kn] = b1.z; sK[kk +  7][kn] = b1.w;
            sK[kk +  8][kn] = b2.x; sK[kk +  9][kn] = b2.y;
            sK[kk + 10][kn] = b2.z; sK[kk + 11][kn] = b2.w;
            sK[kk + 12][kn] = b3.x; sK[kk + 13][kn] = b3.y;
            sK[kk + 14][kn] = b3.z; sK[kk + 15][kn] = b3.w;
            __syncthreads();

            // --- 4x8 outer-product accumulate over BK ---
            #pragma unroll
            for (int k = 0; k < BK; k++) {
                float4 av  = *(const float4*)&sQ[k][trm];
                float4 bv0 = *(const float4*)&sK[k][tcn];
                float4 bv1 = *(const float4*)&sK[k][tcn + 4];
                float a[TM] = {av.x, av.y, av.z, av.w};
                float b[TN] = {bv0.x, bv0.y, bv0.z, bv0.w, bv1.x, bv1.y, bv1.z, bv1.w};
                #pragma unroll
                for (int i = 0; i < TM; i++)
                    #pragma unroll
                    for (int j = 0; j < TN; j++)
                        acc[i][j] = fmaf(a[i], b[j], acc[i][j]);
            }
            __syncthreads();
        }

        // --- stage score tile ---
        #pragma unroll
        for (int i = 0; i < TM; i++) {
            *(float4*)&sS[trm + i][tcn]     = make_float4(acc[i][0], acc[i][1], acc[i][2], acc[i][3]);
            *(float4*)&sS[trm + i][tcn + 4] = make_float4(acc[i][4], acc[i][5], acc[i][6], acc[i][7]);
        }
        __syncthreads();

        // --- scan: Z accumulation + top-3 (cols interleaved: c*4+sq, ascending idx) ---
        #pragma unroll 8
        for (int c = 0; c < 32; c++) {
            const int col = c * 4 + sq;
            const float x = sS[srow][col];
            Z += __expf(x - 1.f);
            if (x > tv2) {
                const int gi = col0 + col;
                if (x > tv0)      { tv2 = tv1; ti2 = ti1; tv1 = tv0; ti1 = ti0; tv0 = x; ti0 = gi; }
                else if (x > tv1) { tv2 = tv1; ti2 = ti1; tv1 = x;  ti1 = gi; }
                else              { tv2 = x;  ti2 = gi; }
            }
        }
        __syncthreads();   // protects sS for next tile + sQ/sK reload
    }

    // --- merge the 4 partial stats per row ---
    mV[srow][sq][0] = tv0; mV[srow][sq][1] = tv1; mV[srow][sq][2] = tv2;
    mI[srow][sq][0] = ti0; mI[srow][sq][1] = ti1; mI[srow][sq][2] = ti2;
    mZ[srow][sq] = Z;
    __syncthreads();

    if (sq == 0) {
        const float Zt = mZ[srow][0] + mZ[srow][1] + mZ[srow][2] + mZ[srow][3];
        float bv0 = -2.f, bv1 = -2.f, bv2 = -2.f;
        int   bi0 = 0x7fffffff, bi1 = 0x7fffffff, bi2 = 0x7fffffff;
        #pragma unroll
        for (int q = 0; q < 4; q++) {
            #pragma unroll
            for (int k = 0; k < 3; k++) {
                const float v = mV[srow][q][k];
                const int  id = mI[srow][q][k];
                if (v > bv0 || (v == bv0 && id < bi0)) {
                    bv2 = bv1; bi2 = bi1; bv1 = bv0; bi1 = bi0; bv0 = v; bi0 = id;
                } else if (v > bv1 || (v == bv1 && id < bi1)) {
                    bv2 = bv1; bi2 = bi1; bv1 = v; bi1 = id;
                } else if (v > bv2 || (v == bv2 && id < bi2)) {
                    bv2 = v; bi2 = id;
                }
            }
        }
        // first-softmax values of the top-3, then second softmax over them
        const float s0 = __expf(bv0 - 1.f) / Zt;
        const float s1 = __expf(bv1 - 1.f) / Zt;
        const float s2 = __expf(bv2 - 1.f) / Zt;
        const float mx = fmaxf(s0, fmaxf(s1, s2));
        const float e0 = __expf(s0 - mx), e1 = __expf(s1 - mx), e2 = __expf(s2 - mx);
        const float inv = 1.f / (e0 + e1 + e2);
        wRow[srow][0] = e0 * inv; wRow[srow][1] = e1 * inv; wRow[srow][2] = e2 * inv;
        iRow[srow][0] = bi0;      iRow[srow][1] = bi1;      iRow[srow][2] = bi2;
    }
    __syncthreads();

    // --- epilogue: gather ORIGINAL embeddings, weighted sum; tid == column ---
    #pragma unroll 4
    for (int r = 0; r < BM; r++) {
        const float w0 = wRow[r][0], w1 = wRow[r][1], w2 = wRow[r][2];
        const int   i0 = iRow[r][0], i1 = iRow[r][1], i2 = iRow[r][2];
        out[(size_t)(row0 + r) * D + tid] =
            w0 * E[(size_t)i0 * D + tid] +
            w1 * E[(size_t)i1 * D + tid] +
            w2 * E[(size_t)i2 * D + tid];
    }
}

// ---------------------------------------------------------------------------
extern "C" void kernel_launch(void* const* d_in, const int* in_sizes, int n_in,
                              void* d_out, int out_size) {
    const float* E = (const float*)d_in[0];
    float* out = (float*)d_out;
    const int n = in_sizes[0] / D;      // 16384
    if (n <= 0) return;

    const int dynSmem = (BK * BM + BK * BN + BM * SSTR) * (int)sizeof(float); // 58368 B
    cudaFuncSetAttribute(neigh_kernel, cudaFuncAttributeMaxDynamicSharedMemorySize, dynSmem);

    norm_kernel<<<n, 256>>>(E);
    neigh_kernel<<<n / BM, 256, dynSmem>>>(E, out, n);
}

// round 5
// speedup vs baseline: 1.3322x; 1.3322x over previous
#include <cuda_runtime.h>
#include <cstdint>

// FindNeighbors sm_103: N=16384, D=256. fp32 scores via 8x8-per-thread
// register-tiled GEMM with packed fma.rn.f32x2, fused streaming softmax-Z
// (poly exp) + top-3, second softmax, 3-way gather.
#define NMAX 16384
#define D    256
#define BM   64      // q rows per CTA
#define BN   256     // keys per tile
#define BK   32      // k chunk
#define SPAD 4
#define SSTR (BN + SPAD)   // 260 (260 mod 32 == 4 -> conflict-free scan)

__device__ float g_En[NMAX * D];   // normalized embeddings (static scratch)

// ---------------- packed f32x2 helpers ----------------
__device__ __forceinline__ uint64_t splat2(float a) {
    uint64_t r; asm("mov.b64 %0, {%1, %1};" : "=l"(r) : "f"(a)); return r;
}
__device__ __forceinline__ void fma2(uint64_t& d, uint64_t a, uint64_t b) {
    asm("fma.rn.f32x2 %0, %1, %2, %0;" : "+l"(d) : "l"(a), "l"(b));
}
__device__ __forceinline__ float2 unpk(uint64_t v) {
    float2 r; asm("mov.b64 {%0, %1}, %2;" : "=f"(r.x), "=f"(r.y) : "l"(v)); return r;
}

// exp(x-1) degree-9 poly (Horner), rel err ~3e-7 on x in [-1,1]; pure FMA pipe.
__device__ __forceinline__ float exp_xm1(float x) {
    float p = 1.0137771196e-06f;
    p = fmaf(p, x, 9.1239940767e-06f);
    p = fmaf(p, x, 7.2991952613e-05f);
    p = fmaf(p, x, 5.1094366829e-04f);
    p = fmaf(p, x, 3.0656620098e-03f);
    p = fmaf(p, x, 1.5328310049e-02f);
    p = fmaf(p, x, 6.1313240195e-02f);
    p = fmaf(p, x, 1.8393972059e-01f);
    p = fmaf(p, x, 3.6787944117e-01f);
    p = fmaf(p, x, 3.6787944117e-01f);
    return p;
}

// ---------------------------------------------------------------------------
// Kernel 1: row-normalize, eps per element before the sum (reference conv.)
// ---------------------------------------------------------------------------
__global__ void norm_kernel(const float* __restrict__ E) {
    int row = blockIdx.x;
    int tid = threadIdx.x;              // 256 == D
    float v = E[row * D + tid];
    float s = v * v + 1e-6f;
    #pragma unroll
    for (int o = 16; o > 0; o >>= 1) s += __shfl_xor_sync(0xffffffffu, s, o);
    __shared__ float red[8];
    if ((tid & 31) == 0) red[tid >> 5] = s;
    __syncthreads();
    if (tid < 8) {
        float t = red[tid];
        #pragma unroll
        for (int o = 4; o > 0; o >>= 1) t += __shfl_xor_sync(0x000000ffu, t, o);
        if (tid == 0) red[0] = t;
    }
    __syncthreads();
    float rinv = rsqrtf(red[0]);
    g_En[row * D + tid] = v * rinv;
}

// ---------------------------------------------------------------------------
// Kernel 2: fused scores + softmax stats + top-3 + second softmax + gather.
// Fixed shift 1.0 (cos < 1 by eps): s_j = exp(x_j-1)/Z, Z = sum exp(x_j-1).
// Softmax monotone => top-3 of softmax == top-3 of raw cos.
// ---------------------------------------------------------------------------
__global__ __launch_bounds__(256, 2)
void neigh_kernel(const float* __restrict__ E, float* __restrict__ out, int n) {
    extern __shared__ float sm[];
    float (*sQ)[BM]   = (float (*)[BM])(sm);                  //  8 KB
    float (*sK)[BN]   = (float (*)[BN])(sm + BK * BM);        // 32 KB
    float (*sS)[SSTR] = (float (*)[SSTR])(sm + BK * BM + BK * BN); // 66.6 KB

    // merge-phase overlay in the (then-dead) score region
    float* mBase = (float*)sS;
    float (*mV)[4][3] = (float (*)[4][3])(mBase);
    int   (*mI)[4][3] = (int   (*)[4][3])(mBase + 768);
    float (*mZ)[4]    = (float (*)[4])   (mBase + 1536);
    float (*wRow)[3]  = (float (*)[3])   (mBase + 1792);
    int   (*iRow)[3]  = (int   (*)[3])   (mBase + 1984);

    const int tid  = threadIdx.x;
    const int row0 = blockIdx.x * BM;

    // 8x32 thread grid, z-split 2x2 of 4x4: rows {tr*4+i, 32+tr*4+i},
    // cols {tc*4+j, 128+tc*4+j}. Warp = fixed tr (broadcast A), tc 0..31
    // (B float4s 128B-contiguous per 8-lane wavefront -> conflict-free).
    const int tr = tid >> 5;
    const int tc = tid & 31;

    // staging maps
    const int qrow = tid >> 2;          // 0..63
    const int qc   = (tid & 3) * 8;     // 8 floats
    // K: one row per thread (tid), 32 floats

    // scan map: 4 threads/row, interleaved cols
    const int srow = tid >> 2;
    const int sq   = tid & 3;

    float tv0 = -2.f, tv1 = -2.f, tv2 = -2.f;
    int   ti0 = 0x7fffffff, ti1 = 0x7fffffff, ti2 = 0x7fffffff;
    float Z = 0.f;

    const float* qbase = &g_En[(size_t)(row0 + qrow) * D + qc];

    const int nTiles = n / BN;          // 64
    for (int kt = 0; kt < nTiles; kt++) {
        const int col0 = kt * BN;
        const float* kbase = &g_En[(size_t)(col0 + tid) * D];

        uint64_t acc[2][2][4][2];       // [rowblk][colblk][i][colpair]
        #pragma unroll
        for (int a = 0; a < 2; a++)
            #pragma unroll
            for (int b = 0; b < 2; b++)
                #pragma unroll
                for (int i = 0; i < 4; i++) { acc[a][b][i][0] = 0ull; acc[a][b][i][1] = 0ull; }

        for (int dk = 0; dk < D; dk += BK) {
            // global loads first (overlap with prior compute before 1st sync)
            float4 q0 = __ldg((const float4*)(qbase + dk));
            float4 q1 = __ldg((const float4*)(qbase + dk + 4));
            float4 kv[8];
            #pragma unroll
            for (int i = 0; i < 8; i++)
                kv[i] = __ldg((const float4*)(kbase + dk + i * 4));

            __syncthreads();            // prior compute done reading smem
            sQ[qc + 0][qrow] = q0.x; sQ[qc + 1][qrow] = q0.y;
            sQ[qc + 2][qrow] = q0.z; sQ[qc + 3][qrow] = q0.w;
            sQ[qc + 4][qrow] = q1.x; sQ[qc + 5][qrow] = q1.y;
            sQ[qc + 6][qrow] = q1.z; sQ[qc + 7][qrow] = q1.w;
            #pragma unroll
            for (int i = 0; i < 8; i++) {
                sK[i * 4 + 0][tid] = kv[i].x;
                sK[i * 4 + 1][tid] = kv[i].y;
                sK[i * 4 + 2][tid] = kv[i].z;
                sK[i * 4 + 3][tid] = kv[i].w;
            }
            __syncthreads();

            #pragma unroll
            for (int k = 0; k < BK; k++) {
                float4 aA = *(const float4*)&sQ[k][tr * 4];
                float4 aB = *(const float4*)&sQ[k][32 + tr * 4];
                ulonglong2 b0 = *(const ulonglong2*)&sK[k][tc * 4];
                ulonglong2 b1 = *(const ulonglong2*)&sK[k][128 + tc * 4];
                uint64_t as[2][4];
                as[0][0] = splat2(aA.x); as[0][1] = splat2(aA.y);
                as[0][2] = splat2(aA.z); as[0][3] = splat2(aA.w);
                as[1][0] = splat2(aB.x); as[1][1] = splat2(aB.y);
                as[1][2] = splat2(aB.z); as[1][3] = splat2(aB.w);
                #pragma unroll
                for (int ib = 0; ib < 2; ib++)
                    #pragma unroll
                    for (int i = 0; i < 4; i++) {
                        fma2(acc[ib][0][i][0], as[ib][i], b0.x);
                        fma2(acc[ib][0][i][1], as[ib][i], b0.y);
                        fma2(acc[ib][1][i][0], as[ib][i], b1.x);
                        fma2(acc[ib][1][i][1], as[ib][i], b1.y);
                    }
            }
        }

        // stage score tile (each thread: 8 rows x two float4 col-chunks)
        #pragma unroll
        for (int ib = 0; ib < 2; ib++)
            #pragma unroll
            for (int i = 0; i < 4; i++) {
                const int r = ib * 32 + tr * 4 + i;
                float2 u0 = unpk(acc[ib][0][i][0]), u1 = unpk(acc[ib][0][i][1]);
                float2 v0 = unpk(acc[ib][1][i][0]), v1 = unpk(acc[ib][1][i][1]);
                *(float4*)&sS[r][tc * 4]       = make_float4(u0.x, u0.y, u1.x, u1.y);
                *(float4*)&sS[r][128 + tc * 4] = make_float4(v0.x, v0.y, v1.x, v1.y);
            }
        __syncthreads();

        // scan: Z + top-3, cols c*4+sq ascending (tie-break safe)
        #pragma unroll 8
        for (int c = 0; c < 64; c++) {
            const int col = c * 4 + sq;
            const float x = sS[srow][col];
            Z += exp_xm1(x);
            if (x > tv2) {
                const int gi = col0 + col;
                if (x > tv0)      { tv2 = tv1; ti2 = ti1; tv1 = tv0; ti1 = ti0; tv0 = x; ti0 = gi; }
                else if (x > tv1) { tv2 = tv1; ti2 = ti1; tv1 = x;  ti1 = gi; }
                else              { tv2 = x;  ti2 = gi; }
            }
        }
        __syncthreads();
    }

    // ---- merge 4 partials per row ----
    mV[srow][sq][0] = tv0; mV[srow][sq][1] = tv1; mV[srow][sq][2] = tv2;
    mI[srow][sq][0] = ti0; mI[srow][sq][1] = ti1; mI[srow][sq][2] = ti2;
    mZ[srow][sq] = Z;
    __syncthreads();

    if (sq == 0) {
        const float Zt = mZ[srow][0] + mZ[srow][1] + mZ[srow][2] + mZ[srow][3];
        float bv0 = -2.f, bv1 = -2.f, bv2 = -2.f;
        int   bi0 = 0x7fffffff, bi1 = 0x7fffffff, bi2 = 0x7fffffff;
        #pragma unroll
        for (int q = 0; q < 4; q++) {
            #pragma unroll
            for (int k = 0; k < 3; k++) {
                const float v = mV[srow][q][k];
                const int  id = mI[srow][q][k];
                if (v > bv0 || (v == bv0 && id < bi0)) {
                    bv2 = bv1; bi2 = bi1; bv1 = bv0; bi1 = bi0; bv0 = v; bi0 = id;
                } else if (v > bv1 || (v == bv1 && id < bi1)) {
                    bv2 = bv1; bi2 = bi1; bv1 = v; bi1 = id;
                } else if (v > bv2 || (v == bv2 && id < bi2)) {
                    bv2 = v; bi2 = id;
                }
            }
        }
        const float s0 = __expf(bv0 - 1.f) / Zt;
        const float s1 = __expf(bv1 - 1.f) / Zt;
        const float s2 = __expf(bv2 - 1.f) / Zt;
        const float mx = fmaxf(s0, fmaxf(s1, s2));
        const float e0 = __expf(s0 - mx), e1 = __expf(s1 - mx), e2 = __expf(s2 - mx);
        const float inv = 1.f / (e0 + e1 + e2);
        wRow[srow][0] = e0 * inv; wRow[srow][1] = e1 * inv; wRow[srow][2] = e2 * inv;
        iRow[srow][0] = bi0;      iRow[srow][1] = bi1;      iRow[srow][2] = bi2;
    }
    __syncthreads();

    // ---- gather epilogue: tid == column ----
    #pragma unroll 4
    for (int r = 0; r < BM; r++) {
        const float w0 = wRow[r][0], w1 = wRow[r][1], w2 = wRow[r][2];
        const int   i0 = iRow[r][0], i1 = iRow[r][1], i2 = iRow[r][2];
        out[(size_t)(row0 + r) * D + tid] =
            w0 * E[(size_t)i0 * D + tid] +
            w1 * E[(size_t)i1 * D + tid] +
            w2 * E[(size_t)i2 * D + tid];
    }
}

// ---------------------------------------------------------------------------
extern "C" void kernel_launch(void* const* d_in, const int* in_sizes, int n_in,
                              void* d_out, int out_size) {
    const float* E = (const float*)d_in[0];
    float* out = (float*)d_out;
    const int n = in_sizes[0] / D;      // 16384
    if (n <= 0) return;

    const int dynSmem = (BK * BM + BK * BN + BM * SSTR) * (int)sizeof(float); // 107520
    cudaFuncSetAttribute(neigh_kernel, cudaFuncAttributeMaxDynamicSharedMemorySize, dynSmem);

    norm_kernel<<<n, 256>>>(E);
    neigh_kernel<<<n / BM, 256, dynSmem>>>(E, out, n);
}

// round 6
// speedup vs baseline: 1.8365x; 1.3785x over previous
#include <cuda_runtime.h>
#include <cstdint>

// FindNeighbors sm_103: N=16384, D=256 fp32.
// S = Xn·Xnᵀ via f32x2 register-tiled GEMM fed by cp.async double buffering
// from pre-transposed operands; fused streaming softmax-Z + warp-private
// top-3; second softmax; 3-way gather.
#define D    256
#define NTOT 16384
#define BM   64
#define BN   256
#define BK   32

__device__ __align__(16) float g_EnT[D * NTOT];      // normalized, [d][n]
__device__ __align__(16) float g_EnDup[D * 2 * NTOT]; // normalized, [d][2n] value-duplicated

// ---------------- helpers ----------------
__device__ __forceinline__ uint32_t smem_u32(const void* p) {
    uint32_t a;
    asm("{ .reg .u64 t; cvta.to.shared.u64 t, %1; cvt.u32.u64 %0, t; }" : "=r"(a) : "l"(p));
    return a;
}
__device__ __forceinline__ void fma2(uint64_t& d, uint64_t a, uint64_t b) {
    asm("fma.rn.f32x2 %0, %1, %2, %0;" : "+l"(d) : "l"(a), "l"(b));
}
__device__ __forceinline__ float2 unpk(uint64_t v) {
    float2 r; asm("mov.b64 {%0, %1}, %2;" : "=f"(r.x), "=f"(r.y) : "l"(v)); return r;
}
__device__ __forceinline__ void cp16(uint32_t dst, const float* src) {
    asm volatile("cp.async.cg.shared.global [%0], [%1], 16;" :: "r"(dst), "l"(src));
}
#define CP_COMMIT() asm volatile("cp.async.commit_group;" ::: "memory")
#define CP_WAIT0()  asm volatile("cp.async.wait_group 0;" ::: "memory")

// exp(x-1), degree-9 Horner, rel ~3e-7 on (-1,1); pure FMA pipe.
__device__ __forceinline__ float exp_xm1(float x) {
    float p = 1.0137771196e-06f;
    p = fmaf(p, x, 9.1239940767e-06f);
    p = fmaf(p, x, 7.2991952613e-05f);
    p = fmaf(p, x, 5.1094366829e-04f);
    p = fmaf(p, x, 3.0656620098e-03f);
    p = fmaf(p, x, 1.5328310049e-02f);
    p = fmaf(p, x, 6.1313240195e-02f);
    p = fmaf(p, x, 1.8393972059e-01f);
    p = fmaf(p, x, 3.6787944117e-01f);
    p = fmaf(p, x, 3.6787944117e-01f);
    return p;
}

// ---------------------------------------------------------------------------
// Kernel 1: normalize (eps per element before sum) + write transposed and
// duplicated-transposed operand arrays. One block = 32 rows.
// ---------------------------------------------------------------------------
__global__ void norm_t_kernel(const float* __restrict__ E) {
    __shared__ float sm[32][257];
    __shared__ float rv[32];
    const int t  = threadIdx.x;          // 256
    const int r0 = blockIdx.x * 32;

    #pragma unroll
    for (int i = 0; i < 8; i++) {
        int idx = t + i * 256;           // float4 id 0..2047
        int r = idx >> 6, c = (idx & 63) * 4;
        float4 v = __ldg((const float4*)(E + (size_t)(r0 + r) * D + c));
        sm[r][c] = v.x; sm[r][c + 1] = v.y; sm[r][c + 2] = v.z; sm[r][c + 3] = v.w;
    }
    __syncthreads();

    const int w = t >> 5, lane = t & 31;
    #pragma unroll
    for (int j = 0; j < 4; j++) {
        int row = w * 4 + j;
        float s = 0.f;
        #pragma unroll
        for (int m = 0; m < 8; m++) { float v = sm[row][lane + m * 32]; s = fmaf(v, v, s); }
        s += 8e-6f;                       // 8 elems x 1e-6 (reference eps convention)
        #pragma unroll
        for (int o = 16; o > 0; o >>= 1) s += __shfl_xor_sync(0xffffffffu, s, o);
        if (lane == 0) rv[row] = rsqrtf(s);
    }
    __syncthreads();

    // thread t owns dimension d = t; write 32 normalized values transposed.
    #pragma unroll
    for (int rb = 0; rb < 8; rb++) {
        float a = sm[rb * 4 + 0][t] * rv[rb * 4 + 0];
        float b = sm[rb * 4 + 1][t] * rv[rb * 4 + 1];
        float c = sm[rb * 4 + 2][t] * rv[rb * 4 + 2];
        float d = sm[rb * 4 + 3][t] * rv[rb * 4 + 3];
        *(float4*)(g_EnT + (size_t)t * NTOT + r0 + rb * 4) = make_float4(a, b, c, d);
        *(float4*)(g_EnDup + (size_t)t * 2 * NTOT + 2 * (r0 + rb * 4))     = make_float4(a, a, b, b);
        *(float4*)(g_EnDup + (size_t)t * 2 * NTOT + 2 * (r0 + rb * 4) + 4) = make_float4(c, c, d, d);
    }
}

// ---------------------------------------------------------------------------
// Kernel 2. smem floats: sQdup [2][32][128] | sK [2][32][256] | stats
// ---------------------------------------------------------------------------
#define SQ_F   (2 * 32 * 128)        // 8192
#define SK_F   (2 * 32 * 256)        // 16384
#define STATS0 (SQ_F + SK_F)         // 24576
#define DYNSMEM ((STATS0 + 64 + 3 * 64 + 3 * 64 + 3 * 64 + 3 * 64 + 16) * 4)

__global__ __launch_bounds__(256, 2)
void neigh_kernel(const float* __restrict__ E, float* __restrict__ out, int n) {
    extern __shared__ float sm[];
    float* sQf = sm;
    float* sKf = sm + SQ_F;
    float* stZ = sm + STATS0;            // [64]
    float* stV = stZ + 64;               // [3][64] planes v0,v1,v2
    int*   stI = (int*)(stV + 192);      // [3][64]
    float* wRow = (float*)(stI + 192);   // [64][3]
    int*   iRow = (int*)(wRow + 192);    // [64][3]

    const int tid  = threadIdx.x;
    const int lane = tid & 31;
    const int tr   = tid >> 5;           // warp id = row group
    const int tc   = lane;
    const int row0 = blockIdx.x * BM;
    const uint32_t sQb = smem_u32(sm);
    const uint32_t sKb = sQb + SQ_F * 4;

    if (tid < 64) {
        stZ[tid] = 0.f;
        stV[tid] = -2.f; stV[64 + tid] = -2.f; stV[128 + tid] = -2.f;
        stI[tid] = 0x7fffffff; stI[64 + tid] = 0x7fffffff; stI[128 + tid] = 0x7fffffff;
    }

    auto issue = [&](int c) {
        const int dk   = (c & 7) * BK;
        const int col0 = (c >> 3) * BN;
        const uint32_t qb = sQb + (uint32_t)((c & 1) * 4096 * 4);
        const uint32_t kb = sKb + (uint32_t)((c & 1) * 8192 * 4);
        #pragma unroll
        for (int i = 0; i < 4; i++) {    // Q dup: 4096 floats = 1024 f4
            int idx = tid + i * 256;
            int qk = idx >> 5, qo = (idx & 31) * 4;
            cp16(qb + (uint32_t)((qk * 128 + qo) * 4),
                 g_EnDup + (size_t)(dk + qk) * 2 * NTOT + 2 * row0 + qo);
        }
        #pragma unroll
        for (int i = 0; i < 8; i++) {    // K: 8192 floats = 2048 f4
            int idx = tid + i * 256;
            int kk = idx >> 6, ko = (idx & 63) * 4;
            cp16(kb + (uint32_t)((kk * 256 + ko) * 4),
                 g_EnT + (size_t)(dk + kk) * NTOT + col0 + ko);
        }
        CP_COMMIT();
    };

    uint64_t acc[2][2][4][2];
    #pragma unroll
    for (int a = 0; a < 2; a++)
        #pragma unroll
        for (int b = 0; b < 2; b++)
            #pragma unroll
            for (int i = 0; i < 4; i++) { acc[a][b][i][0] = 0ull; acc[a][b][i][1] = 0ull; }

    const int nTiles  = n / BN;
    const int nChunks = nTiles * 8;
    issue(0);

    for (int c = 0; c < nChunks; c++) {
        CP_WAIT0();
        __syncthreads();                 // chunk c resident; all warps done with buf c^1
        if (c + 1 < nChunks) issue(c + 1);

        const float* q  = sQf + (c & 1) * 4096;
        const float* kp = sKf + (c & 1) * 8192;
        #pragma unroll
        for (int k = 0; k < BK; k++) {
            // A: duplicated pairs -> ready f32x2 splats (broadcast LDS.128)
            ulonglong2 aA0 = *(const ulonglong2*)(q + k * 128 + tr * 8);
            ulonglong2 aA1 = *(const ulonglong2*)(q + k * 128 + tr * 8 + 4);
            ulonglong2 aB0 = *(const ulonglong2*)(q + k * 128 + 64 + tr * 8);
            ulonglong2 aB1 = *(const ulonglong2*)(q + k * 128 + 64 + tr * 8 + 4);
            ulonglong2 b0  = *(const ulonglong2*)(kp + k * 256 + tc * 4);
            ulonglong2 b1  = *(const ulonglong2*)(kp + k * 256 + 128 + tc * 4);
            uint64_t as0[4] = {aA0.x, aA0.y, aA1.x, aA1.y};
            uint64_t as1[4] = {aB0.x, aB0.y, aB1.x, aB1.y};
            #pragma unroll
            for (int i = 0; i < 4; i++) {
                fma2(acc[0][0][i][0], as0[i], b0.x);
                fma2(acc[0][0][i][1], as0[i], b0.y);
                fma2(acc[0][1][i][0], as0[i], b1.x);
                fma2(acc[0][1][i][1], as0[i], b1.y);
                fma2(acc[1][0][i][0], as1[i], b0.x);
                fma2(acc[1][0][i][1], as1[i], b0.y);
                fma2(acc[1][1][i][0], as1[i], b1.x);
                fma2(acc[1][1][i][1], as1[i], b1.y);
            }
        }

        if ((c & 7) == 7) {
            // ---- in-register epilogue for tile kt; rows are warp-private ----
            const int col0 = (c >> 3) * BN;
            #pragma unroll
            for (int ib = 0; ib < 2; ib++) {
                #pragma unroll
                for (int i = 0; i < 4; i++) {
                    const int row = ib * 32 + tr * 4 + i;
                    float x[8];
                    { float2 u = unpk(acc[ib][0][i][0]); x[0] = u.x; x[1] = u.y; }
                    { float2 u = unpk(acc[ib][0][i][1]); x[2] = u.x; x[3] = u.y; }
                    { float2 u = unpk(acc[ib][1][i][0]); x[4] = u.x; x[5] = u.y; }
                    { float2 u = unpk(acc[ib][1][i][1]); x[6] = u.x; x[7] = u.y; }
                    // Z partial
                    float z = exp_xm1(x[0]) + exp_xm1(x[1]) + exp_xm1(x[2]) + exp_xm1(x[3])
                            + exp_xm1(x[4]) + exp_xm1(x[5]) + exp_xm1(x[6]) + exp_xm1(x[7]);
                    #pragma unroll
                    for (int o = 16; o > 0; o >>= 1) z += __shfl_xor_sync(0xffffffffu, z, o);
                    if (lane == 0) stZ[row] += z;
                    // top-3 fast path
                    float mx = fmaxf(fmaxf(fmaxf(x[0], x[1]), fmaxf(x[2], x[3])),
                                     fmaxf(fmaxf(x[4], x[5]), fmaxf(x[6], x[7])));
                    float rv2 = stV[128 + row];
                    if (__ballot_sync(0xffffffffu, mx > rv2)) {
                        #pragma unroll
                        for (int rnd = 0; rnd < 3; rnd++) {
                            float bv = x[0]; int bj = 0;
                            #pragma unroll
                            for (int j = 1; j < 8; j++)
                                if (x[j] > bv) { bv = x[j]; bj = j; }
                            int bidx = col0 + ((bj >= 4) ? 128 : 0) + tc * 4 + (bj & 3);
                            #pragma unroll
                            for (int o = 16; o > 0; o >>= 1) {
                                float ov = __shfl_xor_sync(0xffffffffu, bv, o);
                                int   oi = __shfl_xor_sync(0xffffffffu, bidx, o);
                                if (ov > bv || (ov == bv && oi < bidx)) { bv = ov; bidx = oi; }
                            }
                            if (lane == 0) {
                                float r0v = stV[row], r1v = stV[64 + row], r2v = stV[128 + row];
                                int   r0i = stI[row], r1i = stI[64 + row];
                                if (bv > r0v) {
                                    stV[128 + row] = r1v; stI[128 + row] = r1i;
                                    stV[64 + row] = r0v;  stI[64 + row] = r0i;
                                    stV[row] = bv;        stI[row] = bidx;
                                } else if (bv > r1v) {
                                    stV[128 + row] = r1v; stI[128 + row] = r1i;
                                    stV[64 + row] = bv;   stI[64 + row] = bidx;
                                } else if (bv > r2v) {
                                    stV[128 + row] = bv;  stI[128 + row] = bidx;
                                }
                            }
                            #pragma unroll
                            for (int j = 0; j < 8; j++) {
                                int cj = col0 + ((j >= 4) ? 128 : 0) + tc * 4 + (j & 3);
                                if (cj == bidx) x[j] = -3.f;
                            }
                        }
                    }
                }
            }
            // reset accumulators
            #pragma unroll
            for (int a = 0; a < 2; a++)
                #pragma unroll
                for (int b = 0; b < 2; b++)
                    #pragma unroll
                    for (int i = 0; i < 4; i++) { acc[a][b][i][0] = 0ull; acc[a][b][i][1] = 0ull; }
        }
    }

    __syncthreads();
    if (tid < 64) {
        const float Zt = stZ[tid];
        const float s0 = __expf(stV[tid] - 1.f) / Zt;
        const float s1 = __expf(stV[64 + tid] - 1.f) / Zt;
        const float s2 = __expf(stV[128 + tid] - 1.f) / Zt;
        const float mxs = fmaxf(s0, fmaxf(s1, s2));
        const float e0 = __expf(s0 - mxs), e1 = __expf(s1 - mxs), e2 = __expf(s2 - mxs);
        const float inv = 1.f / (e0 + e1 + e2);
        wRow[tid * 3 + 0] = e0 * inv; wRow[tid * 3 + 1] = e1 * inv; wRow[tid * 3 + 2] = e2 * inv;
        iRow[tid * 3 + 0] = stI[tid]; iRow[tid * 3 + 1] = stI[64 + tid]; iRow[tid * 3 + 2] = stI[128 + tid];
    }
    __syncthreads();

    #pragma unroll 4
    for (int r = 0; r < BM; r++) {
        const float w0 = wRow[r * 3 + 0], w1 = wRow[r * 3 + 1], w2 = wRow[r * 3 + 2];
        const int   i0 = iRow[r * 3 + 0], i1 = iRow[r * 3 + 1], i2 = iRow[r * 3 + 2];
        out[(size_t)(row0 + r) * D + tid] =
            w0 * E[(size_t)i0 * D + tid] +
            w1 * E[(size_t)i1 * D + tid] +
            w2 * E[(size_t)i2 * D + tid];
    }
}

// ---------------------------------------------------------------------------
extern "C" void kernel_launch(void* const* d_in, const int* in_sizes, int n_in,
                              void* d_out, int out_size) {
    const float* E = (const float*)d_in[0];
    float* out = (float*)d_out;
    const int n = in_sizes[0] / D;      // 16384
    if (n <= 0) return;

    cudaFuncSetAttribute(neigh_kernel, cudaFuncAttributeMaxDynamicSharedMemorySize, DYNSMEM);

    norm_t_kernel<<<n / 32, 256>>>(E);
    neigh_kernel<<<n / BM, 256, DYNSMEM>>>(E, out, n);
}

// round 7
// speedup vs baseline: 2.8645x; 1.5598x over previous
#include <cuda_runtime.h>
#include <cstdint>

// FindNeighbors sm_103: N=16384, D=256 fp32.
// Symmetric-GEMM: S computed once per unordered tile pair (128x128 tiles).
// f32x2 FMAs, cp.async double buffering, per-block row+col partial stats
// (top-3 + Z) to a global slot buffer, then a reduce+gather pass.
#define D    256
#define NTOT 16384
#define TILE 128
#define NT   (NTOT / TILE)    // 128

__device__ __align__(16) float g_EnT[D * NTOT];        // normalized, [d][n]
__device__ __align__(16) float g_EnDup[D * 2 * NTOT];  // normalized, [d][2n] dup'd
__device__ float4 g_part[NT][NTOT][2];                 // [slot][row]: 32B partial stats

// ---------------- helpers ----------------
__device__ __forceinline__ uint32_t smem_u32(const void* p) {
    uint32_t a;
    asm("{ .reg .u64 t; cvta.to.shared.u64 t, %1; cvt.u32.u64 %0, t; }" : "=r"(a) : "l"(p));
    return a;
}
__device__ __forceinline__ void fma2(uint64_t& d, uint64_t a, uint64_t b) {
    asm("fma.rn.f32x2 %0, %1, %2, %0;" : "+l"(d) : "l"(a), "l"(b));
}
__device__ __forceinline__ float2 unpk(uint64_t v) {
    float2 r; asm("mov.b64 {%0, %1}, %2;" : "=f"(r.x), "=f"(r.y) : "l"(v)); return r;
}
__device__ __forceinline__ void cp16(uint32_t dst, const float* src) {
    asm volatile("cp.async.cg.shared.global [%0], [%1], 16;" :: "r"(dst), "l"(src));
}
#define CP_COMMIT() asm volatile("cp.async.commit_group;" ::: "memory")
#define CP_WAIT0()  asm volatile("cp.async.wait_group 0;" ::: "memory")

// exp(x-1), degree-9 Horner, rel ~3e-7 on (-1,1); pure FMA pipe.
__device__ __forceinline__ float exp_xm1(float x) {
    float p = 1.0137771196e-06f;
    p = fmaf(p, x, 9.1239940767e-06f);
    p = fmaf(p, x, 7.2991952613e-05f);
    p = fmaf(p, x, 5.1094366829e-04f);
    p = fmaf(p, x, 3.0656620098e-03f);
    p = fmaf(p, x, 1.5328310049e-02f);
    p = fmaf(p, x, 6.1313240195e-02f);
    p = fmaf(p, x, 1.8393972059e-01f);
    p = fmaf(p, x, 3.6787944117e-01f);
    p = fmaf(p, x, 3.6787944117e-01f);
    return p;
}

// top-3 insert with jax.lax.top_k tie-break (equal value -> lower index)
__device__ __forceinline__ void ins3(float& v0, float& v1, float& v2,
                                     int& i0, int& i1, int& i2,
                                     float nv, int ni) {
    if (nv > v0 || (nv == v0 && ni < i0)) {
        v2 = v1; i2 = i1; v1 = v0; i1 = i0; v0 = nv; i0 = ni;
    } else if (nv > v1 || (nv == v1 && ni < i1)) {
        v2 = v1; i2 = i1; v1 = nv; i1 = ni;
    } else if (nv > v2 || (nv == v2 && ni < i2)) {
        v2 = nv; i2 = ni;
    }
}

// ---------------------------------------------------------------------------
// Kernel 1: normalize (eps per element before sum, reference convention) and
// write transposed + duplicated-transposed operands. One block = 32 rows.
// ---------------------------------------------------------------------------
__global__ void norm_t_kernel(const float* __restrict__ E) {
    __shared__ float sm[32][257];
    __shared__ float rv[32];
    const int t  = threadIdx.x;          // 256
    const int r0 = blockIdx.x * 32;

    #pragma unroll
    for (int i = 0; i < 8; i++) {
        int idx = t + i * 256;
        int r = idx >> 6, c = (idx & 63) * 4;
        float4 v = __ldg((const float4*)(E + (size_t)(r0 + r) * D + c));
        sm[r][c] = v.x; sm[r][c + 1] = v.y; sm[r][c + 2] = v.z; sm[r][c + 3] = v.w;
    }
    __syncthreads();

    const int w = t >> 5, lane = t & 31;
    #pragma unroll
    for (int j = 0; j < 4; j++) {
        int row = w * 4 + j;
        float s = 0.f;
        #pragma unroll
        for (int m = 0; m < 8; m++) { float v = sm[row][lane + m * 32]; s = fmaf(v, v, s); }
        s += 8e-6f;                       // 8 elems x 1e-6
        #pragma unroll
        for (int o = 16; o > 0; o >>= 1) s += __shfl_xor_sync(0xffffffffu, s, o);
        if (lane == 0) rv[row] = rsqrtf(s);
    }
    __syncthreads();

    #pragma unroll
    for (int rb = 0; rb < 8; rb++) {
        float a = sm[rb * 4 + 0][t] * rv[rb * 4 + 0];
        float b = sm[rb * 4 + 1][t] * rv[rb * 4 + 1];
        float c = sm[rb * 4 + 2][t] * rv[rb * 4 + 2];
        float d = sm[rb * 4 + 3][t] * rv[rb * 4 + 3];
        *(float4*)(g_EnT + (size_t)t * NTOT + r0 + rb * 4) = make_float4(a, b, c, d);
        *(float4*)(g_EnDup + (size_t)t * 2 * NTOT + 2 * (r0 + rb * 4))     = make_float4(a, a, b, b);
        *(float4*)(g_EnDup + (size_t)t * 2 * NTOT + 2 * (r0 + rb * 4) + 4) = make_float4(c, c, d, d);
    }
}

// ---------------------------------------------------------------------------
// Phase 1: one CTA per tile pair (ti <= tj). 256 thr, 8x8 f32 per thread.
// smem: double-buffered operands (24576 f); epilogue overlays score tile
// sS[128][132] + colZ buffer in the same region.
// ---------------------------------------------------------------------------
#define SM_FLOATS 24576
#define DYNSMEM   (SM_FLOATS * 4)

__global__ __launch_bounds__(256, 2)
void sym_kernel() {
    const int ti = blockIdx.y, tj = blockIdx.x;
    if (tj < ti) return;
    extern __shared__ float sm[];
    const int tid = threadIdx.x;
    const int tr = tid >> 4, tc = tid & 15;       // 16x16 grid; rows tr*8.., cols tc*8..
    const uint32_t smb = smem_u32(sm);

    uint64_t acc[8][4];
    #pragma unroll
    for (int i = 0; i < 8; i++)
        #pragma unroll
        for (int p = 0; p < 4; p++) acc[i][p] = 0ull;

    auto issue = [&](int c) {
        const int dk = c * 32;
        const uint32_t qb = smb + (uint32_t)(((c & 1) * 12288) * 4);
        const uint32_t kb = qb + 8192u * 4u;
        #pragma unroll
        for (int i = 0; i < 8; i++) {            // Q dup: 32 k-rows x 256 f
            int idx = tid + i * 256;
            int qk = idx >> 6, qo = (idx & 63) * 4;
            cp16(qb + (uint32_t)((qk * 256 + qo) * 4),
                 g_EnDup + (size_t)(dk + qk) * (2 * NTOT) + 2 * ti * TILE + qo);
        }
        #pragma unroll
        for (int i = 0; i < 4; i++) {            // K: 32 k-rows x 128 f
            int idx = tid + i * 256;
            int kk = idx >> 5, ko = (idx & 31) * 4;
            cp16(kb + (uint32_t)((kk * 128 + ko) * 4),
                 g_EnT + (size_t)(dk + kk) * NTOT + tj * TILE + ko);
        }
        CP_COMMIT();
    };

    issue(0);
    #pragma unroll 1
    for (int c = 0; c < 8; c++) {
        CP_WAIT0();
        __syncthreads();
        if (c < 7) issue(c + 1);
        const float* q  = sm + (c & 1) * 12288;
        const float* kp = q + 8192;
        #pragma unroll
        for (int k = 0; k < 32; k++) {
            ulonglong2 A0 = *(const ulonglong2*)(q + k * 256 + tr * 16);
            ulonglong2 A1 = *(const ulonglong2*)(q + k * 256 + tr * 16 + 4);
            ulonglong2 A2 = *(const ulonglong2*)(q + k * 256 + tr * 16 + 8);
            ulonglong2 A3 = *(const ulonglong2*)(q + k * 256 + tr * 16 + 12);
            ulonglong2 B0 = *(const ulonglong2*)(kp + k * 128 + tc * 8);
            ulonglong2 B1 = *(const ulonglong2*)(kp + k * 128 + tc * 8 + 4);
            uint64_t as[8] = {A0.x, A0.y, A1.x, A1.y, A2.x, A2.y, A3.x, A3.y};
            uint64_t bs[4] = {B0.x, B0.y, B1.x, B1.y};
            #pragma unroll
            for (int i = 0; i < 8; i++)
                #pragma unroll
                for (int p = 0; p < 4; p++)
                    fma2(acc[i][p], as[i], bs[p]);
        }
    }

    // ---- row stats (pure registers) + column-Z partials ----
    float colz[8];
    #pragma unroll
    for (int j = 0; j < 8; j++) colz[j] = 0.f;

    const int rowg = ti * TILE + tr * 8;
    const int colg = tj * TILE + tc * 8;

    #pragma unroll
    for (int i = 0; i < 8; i++) {
        float x[8];
        #pragma unroll
        for (int p = 0; p < 4; p++) {
            float2 u = unpk(acc[i][p]);
            x[2 * p] = u.x; x[2 * p + 1] = u.y;
        }
        float rz = 0.f;
        #pragma unroll
        for (int j = 0; j < 8; j++) {
            float e = exp_xm1(x[j]);
            rz += e; colz[j] += e;
        }
        float v0 = -2.f, v1 = -2.f, v2 = -2.f;
        int i0 = 0x7fffffff, i1 = 0x7fffffff, i2 = 0x7fffffff;
        #pragma unroll
        for (int j = 0; j < 8; j++)          // ascending idx, strict > => tie-safe
            if (x[j] > v2) ins3(v0, v1, v2, i0, i1, i2, x[j], colg + j);
        #pragma unroll
        for (int o = 1; o < 16; o <<= 1) {   // merge across the 16-thread row group
            float ov0 = __shfl_xor_sync(0xffffffffu, v0, o);
            float ov1 = __shfl_xor_sync(0xffffffffu, v1, o);
            float ov2 = __shfl_xor_sync(0xffffffffu, v2, o);
            int oi0 = __shfl_xor_sync(0xffffffffu, i0, o);
            int oi1 = __shfl_xor_sync(0xffffffffu, i1, o);
            int oi2 = __shfl_xor_sync(0xffffffffu, i2, o);
            rz += __shfl_xor_sync(0xffffffffu, rz, o);
            ins3(v0, v1, v2, i0, i1, i2, ov0, oi0);
            ins3(v0, v1, v2, i0, i1, i2, ov1, oi1);
            ins3(v0, v1, v2, i0, i1, i2, ov2, oi2);
        }
        if (tc == 0) {
            g_part[tj][rowg + i][0] = make_float4(v0, v1, v2, __int_as_float(i0));
            g_part[tj][rowg + i][1] = make_float4(__int_as_float(i1), __int_as_float(i2), rz, 0.f);
        }
    }

    // ---- column stats (off-diagonal blocks only; block-uniform branch) ----
    if (ti != tj) {
        __syncthreads();                      // operand smem dead -> reuse as sS
        #pragma unroll
        for (int i = 0; i < 8; i++) {
            const int r = tr * 8 + i;
            float2 u0 = unpk(acc[i][0]), u1 = unpk(acc[i][1]);
            float2 u2 = unpk(acc[i][2]), u3 = unpk(acc[i][3]);
            *(float4*)&sm[r * 132 + tc * 8]     = make_float4(u0.x, u0.y, u1.x, u1.y);
            *(float4*)&sm[r * 132 + tc * 8 + 4] = make_float4(u2.x, u2.y, u3.x, u3.y);
        }
        #pragma unroll
        for (int j = 0; j < 8; j++)           // pair-merge tr vs tr^1 (lanes l, l^16)
            colz[j] += __shfl_xor_sync(0xffffffffu, colz[j], 16);
        float* czb = sm + 128 * 132;          // [8][128]
        if ((tid & 16) == 0) {
            const int g = tid >> 5;
            #pragma unroll
            for (int j = 0; j < 8; j++) czb[g * 128 + tc * 8 + j] = colz[j];
        }
        __syncthreads();
        if (tid < 128) {
            const int col = tid;
            float cz = 0.f;
            #pragma unroll
            for (int g = 0; g < 8; g++) cz += czb[g * 128 + col];
            float v0 = -2.f, v1 = -2.f, v2 = -2.f;
            int i0 = 0x7fffffff, i1 = 0x7fffffff, i2 = 0x7fffffff;
            #pragma unroll 8
            for (int r = 0; r < 128; r++) {   // ascending idx, strict >
                float xv = sm[r * 132 + col];
                if (xv > v2) ins3(v0, v1, v2, i0, i1, i2, xv, ti * TILE + r);
            }
            g_part[ti][tj * TILE + col][0] = make_float4(v0, v1, v2, __int_as_float(i0));
            g_part[ti][tj * TILE + col][1] = make_float4(__int_as_float(i1), __int_as_float(i2), cz, 0.f);
        }
    }
}

// ---------------------------------------------------------------------------
// Phase 2: per row, merge 128 slots -> final top-3 + Z, second softmax, gather.
// One warp per row (8 rows / 256-thread block).
// ---------------------------------------------------------------------------
__global__ __launch_bounds__(256, 2)
void reduce_kernel(const float* __restrict__ E, float* __restrict__ out) {
    const int row  = blockIdx.x * 8 + (threadIdx.x >> 5);
    const int lane = threadIdx.x & 31;

    float v0 = -2.f, v1 = -2.f, v2 = -2.f;
    int   i0 = 0x7fffffff, i1 = 0x7fffffff, i2 = 0x7fffffff;
    float Z = 0.f;
    #pragma unroll
    for (int s = 0; s < 4; s++) {
        const int slot = lane * 4 + s;       // ascending slots => ascending idx ranges
        float4 h0 = __ldg(&g_part[slot][row][0]);
        float4 h1 = __ldg(&g_part[slot][row][1]);
        Z += h1.z;
        ins3(v0, v1, v2, i0, i1, i2, h0.x, __float_as_int(h0.w));
        ins3(v0, v1, v2, i0, i1, i2, h0.y, __float_as_int(h1.x));
        ins3(v0, v1, v2, i0, i1, i2, h0.z, __float_as_int(h1.y));
    }
    #pragma unroll
    for (int o = 1; o < 32; o <<= 1) {
        float ov0 = __shfl_xor_sync(0xffffffffu, v0, o);
        float ov1 = __shfl_xor_sync(0xffffffffu, v1, o);
        float ov2 = __shfl_xor_sync(0xffffffffu, v2, o);
        int oi0 = __shfl_xor_sync(0xffffffffu, i0, o);
        int oi1 = __shfl_xor_sync(0xffffffffu, i1, o);
        int oi2 = __shfl_xor_sync(0xffffffffu, i2, o);
        Z += __shfl_xor_sync(0xffffffffu, Z, o);
        ins3(v0, v1, v2, i0, i1, i2, ov0, oi0);
        ins3(v0, v1, v2, i0, i1, i2, ov1, oi1);
        ins3(v0, v1, v2, i0, i1, i2, ov2, oi2);
    }

    const float s0 = __expf(v0 - 1.f) / Z;
    const float s1 = __expf(v1 - 1.f) / Z;
    const float s2 = __expf(v2 - 1.f) / Z;
    const float mx = fmaxf(s0, fmaxf(s1, s2));
    const float e0 = __expf(s0 - mx), e1 = __expf(s1 - mx), e2 = __expf(s2 - mx);
    const float inv = 1.f / (e0 + e1 + e2);
    const float w0 = e0 * inv, w1 = e1 * inv, w2 = e2 * inv;

    const float* p0 = E + (size_t)i0 * D;
    const float* p1 = E + (size_t)i1 * D;
    const float* p2 = E + (size_t)i2 * D;
    #pragma unroll
    for (int t = 0; t < 2; t++) {
        const int cc = lane * 8 + t * 4;
        float4 a = __ldg((const float4*)(p0 + cc));
        float4 b = __ldg((const float4*)(p1 + cc));
        float4 c = __ldg((const float4*)(p2 + cc));
        float4 o;
        o.x = w0 * a.x + w1 * b.x + w2 * c.x;
        o.y = w0 * a.y + w1 * b.y + w2 * c.y;
        o.z = w0 * a.z + w1 * b.z + w2 * c.z;
        o.w = w0 * a.w + w1 * b.w + w2 * c.w;
        *(float4*)(out + (size_t)row * D + cc) = o;
    }
}

// ---------------------------------------------------------------------------
extern "C" void kernel_launch(void* const* d_in, const int* in_sizes, int n_in,
                              void* d_out, int out_size) {
    const float* E = (const float*)d_in[0];
    float* out = (float*)d_out;
    const int n = in_sizes[0] / D;      // 16384
    if (n <= 0) return;

    cudaFuncSetAttribute(sym_kernel, cudaFuncAttributeMaxDynamicSharedMemorySize, DYNSMEM);

    norm_t_kernel<<<NTOT / 32, 256>>>(E);
    dim3 g1(NT, NT);
    sym_kernel<<<g1, 256, DYNSMEM>>>();
    reduce_kernel<<<NTOT / 8, 256>>>(E, out);
}

// round 8
// speedup vs baseline: 3.1915x; 1.1142x over previous
#include <cuda_runtime.h>
#include <cstdint>

// FindNeighbors sm_103: N=16384, D=256 fp32.
// Symmetric-GEMM (one pass per unordered 128x128 tile pair), f32x2 FMAs with
// non-duplicated operands (LDS-balanced), cp.async double buffering,
// per-block row+col partial stats (top-3 + Z) -> slot buffer -> reduce+gather.
#define D    256
#define NTOT 16384
#define TILE 128
#define NT   (NTOT / TILE)    // 128

__device__ __align__(16) float g_EnT[D * NTOT];        // normalized, [d][n]
__device__ float4 g_part[NT][NTOT][2];                 // [slot][row]: 32B partial stats

// ---------------- helpers ----------------
__device__ __forceinline__ uint32_t smem_u32(const void* p) {
    uint32_t a;
    asm("{ .reg .u64 t; cvta.to.shared.u64 t, %1; cvt.u32.u64 %0, t; }" : "=r"(a) : "l"(p));
    return a;
}
__device__ __forceinline__ uint64_t splat2(float a) {
    uint64_t r; asm("mov.b64 %0, {%1, %1};" : "=l"(r) : "f"(a)); return r;
}
__device__ __forceinline__ void fma2(uint64_t& d, uint64_t a, uint64_t b) {
    asm("fma.rn.f32x2 %0, %1, %2, %0;" : "+l"(d) : "l"(a), "l"(b));
}
__device__ __forceinline__ float2 unpk(uint64_t v) {
    float2 r; asm("mov.b64 {%0, %1}, %2;" : "=f"(r.x), "=f"(r.y) : "l"(v)); return r;
}
__device__ __forceinline__ void cp16(uint32_t dst, const float* src) {
    asm volatile("cp.async.cg.shared.global [%0], [%1], 16;" :: "r"(dst), "l"(src));
}
#define CP_COMMIT() asm volatile("cp.async.commit_group;" ::: "memory")
#define CP_WAIT0()  asm volatile("cp.async.wait_group 0;" ::: "memory")

// exp(x-1), degree-9 Horner, rel ~3e-7 on (-1,1); pure FMA pipe.
__device__ __forceinline__ float exp_xm1(float x) {
    float p = 1.0137771196e-06f;
    p = fmaf(p, x, 9.1239940767e-06f);
    p = fmaf(p, x, 7.2991952613e-05f);
    p = fmaf(p, x, 5.1094366829e-04f);
    p = fmaf(p, x, 3.0656620098e-03f);
    p = fmaf(p, x, 1.5328310049e-02f);
    p = fmaf(p, x, 6.1313240195e-02f);
    p = fmaf(p, x, 1.8393972059e-01f);
    p = fmaf(p, x, 3.6787944117e-01f);
    p = fmaf(p, x, 3.6787944117e-01f);
    return p;
}

// top-3 insert with jax.lax.top_k tie-break (equal value -> lower index)
__device__ __forceinline__ void ins3(float& v0, float& v1, float& v2,
                                     int& i0, int& i1, int& i2,
                                     float nv, int ni) {
    if (nv > v0 || (nv == v0 && ni < i0)) {
        v2 = v1; i2 = i1; v1 = v0; i1 = i0; v0 = nv; i0 = ni;
    } else if (nv > v1 || (nv == v1 && ni < i1)) {
        v2 = v1; i2 = i1; v1 = nv; i1 = ni;
    } else if (nv > v2 || (nv == v2 && ni < i2)) {
        v2 = nv; i2 = ni;
    }
}

// ---------------------------------------------------------------------------
// Kernel 1: normalize (eps per element before sum) + transposed operand.
// ---------------------------------------------------------------------------
__global__ void norm_t_kernel(const float* __restrict__ E) {
    __shared__ float sm[32][257];
    __shared__ float rv[32];
    const int t  = threadIdx.x;          // 256
    const int r0 = blockIdx.x * 32;

    #pragma unroll
    for (int i = 0; i < 8; i++) {
        int idx = t + i * 256;
        int r = idx >> 6, c = (idx & 63) * 4;
        float4 v = __ldg((const float4*)(E + (size_t)(r0 + r) * D + c));
        sm[r][c] = v.x; sm[r][c + 1] = v.y; sm[r][c + 2] = v.z; sm[r][c + 3] = v.w;
    }
    __syncthreads();

    const int w = t >> 5, lane = t & 31;
    #pragma unroll
    for (int j = 0; j < 4; j++) {
        int row = w * 4 + j;
        float s = 0.f;
        #pragma unroll
        for (int m = 0; m < 8; m++) { float v = sm[row][lane + m * 32]; s = fmaf(v, v, s); }
        s += 8e-6f;                       // 8 elems x 1e-6 (reference eps convention)
        #pragma unroll
        for (int o = 16; o > 0; o >>= 1) s += __shfl_xor_sync(0xffffffffu, s, o);
        if (lane == 0) rv[row] = rsqrtf(s);
    }
    __syncthreads();

    #pragma unroll
    for (int rb = 0; rb < 8; rb++) {
        float a = sm[rb * 4 + 0][t] * rv[rb * 4 + 0];
        float b = sm[rb * 4 + 1][t] * rv[rb * 4 + 1];
        float c = sm[rb * 4 + 2][t] * rv[rb * 4 + 2];
        float d = sm[rb * 4 + 3][t] * rv[rb * 4 + 3];
        *(float4*)(g_EnT + (size_t)t * NTOT + r0 + rb * 4) = make_float4(a, b, c, d);
    }
}

// ---------------------------------------------------------------------------
// Phase 1: one CTA per tile pair (ti <= tj). 256 thr, 8x8 f32 per thread.
// Operand smem: 2 x (32x128 A + 32x128 B) = 16384 f (64 KB).
// Epilogue overlays sS[128][132] + colZ [8][128] = 17920 f (70 KB).
// ---------------------------------------------------------------------------
#define DYNSMEM ((128 * 132 + 8 * 128) * 4)   // 71680 B (covers both phases)

__global__ __launch_bounds__(256, 2)
void sym_kernel() {
    const int ti = blockIdx.y, tj = blockIdx.x;
    if (tj < ti) return;
    extern __shared__ float sm[];
    const int tid = threadIdx.x;
    const int tr = tid >> 4, tc = tid & 15;       // 16x16 grid; rows tr*8.., cols tc*8..
    const uint32_t smb = smem_u32(sm);

    uint64_t acc[8][4];
    #pragma unroll
    for (int i = 0; i < 8; i++)
        #pragma unroll
        for (int p = 0; p < 4; p++) acc[i][p] = 0ull;

    auto issue = [&](int c) {
        const int dk = c * 32;
        const uint32_t qb = smb + (uint32_t)(((c & 1) * 8192) * 4);
        const uint32_t kb = qb + 4096u * 4u;
        #pragma unroll
        for (int i = 0; i < 4; i++) {            // A: 32 k-rows x 128 f (ti strip)
            int idx = tid + i * 256;
            int qk = idx >> 5, qo = (idx & 31) * 4;
            cp16(qb + (uint32_t)((qk * 128 + qo) * 4),
                 g_EnT + (size_t)(dk + qk) * NTOT + ti * TILE + qo);
        }
        #pragma unroll
        for (int i = 0; i < 4; i++) {            // B: 32 k-rows x 128 f (tj strip)
            int idx = tid + i * 256;
            int kk = idx >> 5, ko = (idx & 31) * 4;
            cp16(kb + (uint32_t)((kk * 128 + ko) * 4),
                 g_EnT + (size_t)(dk + kk) * NTOT + tj * TILE + ko);
        }
        CP_COMMIT();
    };

    issue(0);
    #pragma unroll 1
    for (int c = 0; c < 8; c++) {
        CP_WAIT0();
        __syncthreads();
        if (c < 7) issue(c + 1);
        const float* q  = sm + (c & 1) * 8192;
        const float* kp = q + 4096;
        #pragma unroll
        for (int k = 0; k < 32; k++) {
            float4 a0 = *(const float4*)(q + k * 128 + tr * 8);
            float4 a1 = *(const float4*)(q + k * 128 + tr * 8 + 4);
            ulonglong2 B0 = *(const ulonglong2*)(kp + k * 128 + tc * 8);
            ulonglong2 B1 = *(const ulonglong2*)(kp + k * 128 + tc * 8 + 4);
            uint64_t as[8];
            as[0] = splat2(a0.x); as[1] = splat2(a0.y);
            as[2] = splat2(a0.z); as[3] = splat2(a0.w);
            as[4] = splat2(a1.x); as[5] = splat2(a1.y);
            as[6] = splat2(a1.z); as[7] = splat2(a1.w);
            uint64_t bs[4] = {B0.x, B0.y, B1.x, B1.y};
            #pragma unroll
            for (int i = 0; i < 8; i++)
                #pragma unroll
                for (int p = 0; p < 4; p++)
                    fma2(acc[i][p], as[i], bs[p]);
        }
    }

    // ---- row stats (pure registers) + column-Z partials ----
    float colz[8];
    #pragma unroll
    for (int j = 0; j < 8; j++) colz[j] = 0.f;

    const int rowg = ti * TILE + tr * 8;
    const int colg = tj * TILE + tc * 8;

    #pragma unroll
    for (int i = 0; i < 8; i++) {
        float x[8];
        #pragma unroll
        for (int p = 0; p < 4; p++) {
            float2 u = unpk(acc[i][p]);
            x[2 * p] = u.x; x[2 * p + 1] = u.y;
        }
        float rz = 0.f;
        #pragma unroll
        for (int j = 0; j < 8; j++) {
            float e = exp_xm1(x[j]);
            rz += e; colz[j] += e;
        }
        float v0 = -2.f, v1 = -2.f, v2 = -2.f;
        int i0 = 0x7fffffff, i1 = 0x7fffffff, i2 = 0x7fffffff;
        #pragma unroll
        for (int j = 0; j < 8; j++)          // ascending idx, strict > => tie-safe
            if (x[j] > v2) ins3(v0, v1, v2, i0, i1, i2, x[j], colg + j);
        #pragma unroll
        for (int o = 1; o < 16; o <<= 1) {   // merge across the 16-thread row group
            float ov0 = __shfl_xor_sync(0xffffffffu, v0, o);
            float ov1 = __shfl_xor_sync(0xffffffffu, v1, o);
            float ov2 = __shfl_xor_sync(0xffffffffu, v2, o);
            int oi0 = __shfl_xor_sync(0xffffffffu, i0, o);
            int oi1 = __shfl_xor_sync(0xffffffffu, i1, o);
            int oi2 = __shfl_xor_sync(0xffffffffu, i2, o);
            rz += __shfl_xor_sync(0xffffffffu, rz, o);
            ins3(v0, v1, v2, i0, i1, i2, ov0, oi0);
            ins3(v0, v1, v2, i0, i1, i2, ov1, oi1);
            ins3(v0, v1, v2, i0, i1, i2, ov2, oi2);
        }
        if (tc == 0) {
            g_part[tj][rowg + i][0] = make_float4(v0, v1, v2, __int_as_float(i0));
            g_part[tj][rowg + i][1] = make_float4(__int_as_float(i1), __int_as_float(i2), rz, 0.f);
        }
    }

    // ---- column stats (off-diagonal blocks only; block-uniform branch) ----
    if (ti != tj) {
        __syncthreads();                      // operand smem dead -> reuse as sS
        #pragma unroll
        for (int i = 0; i < 8; i++) {
            const int r = tr * 8 + i;
            float2 u0 = unpk(acc[i][0]), u1 = unpk(acc[i][1]);
            float2 u2 = unpk(acc[i][2]), u3 = unpk(acc[i][3]);
            *(float4*)&sm[r * 132 + tc * 8]     = make_float4(u0.x, u0.y, u1.x, u1.y);
            *(float4*)&sm[r * 132 + tc * 8 + 4] = make_float4(u2.x, u2.y, u3.x, u3.y);
        }
        #pragma unroll
        for (int j = 0; j < 8; j++)           // pair-merge tr vs tr^1 (lanes l, l^16)
            colz[j] += __shfl_xor_sync(0xffffffffu, colz[j], 16);
        float* czb = sm + 128 * 132;          // [8][128]
        if ((tid & 16) == 0) {
            const int g = tid >> 5;
            #pragma unroll
            for (int j = 0; j < 8; j++) czb[g * 128 + tc * 8 + j] = colz[j];
        }
        __syncthreads();
        if (tid < 128) {
            const int col = tid;
            float cz = 0.f;
            #pragma unroll
            for (int g = 0; g < 8; g++) cz += czb[g * 128 + col];
            float v0 = -2.f, v1 = -2.f, v2 = -2.f;
            int i0 = 0x7fffffff, i1 = 0x7fffffff, i2 = 0x7fffffff;
            #pragma unroll 8
            for (int r = 0; r < 128; r++) {   // ascending idx, strict >
                float xv = sm[r * 132 + col];
                if (xv > v2) ins3(v0, v1, v2, i0, i1, i2, xv, ti * TILE + r);
            }
            g_part[ti][tj * TILE + col][0] = make_float4(v0, v1, v2, __int_as_float(i0));
            g_part[ti][tj * TILE + col][1] = make_float4(__int_as_float(i1), __int_as_float(i2), cz, 0.f);
        }
    }
}

// ---------------------------------------------------------------------------
// Phase 2: per row, merge 128 slots -> final top-3 + Z, second softmax, gather.
// ---------------------------------------------------------------------------
__global__ __launch_bounds__(256, 2)
void reduce_kernel(const float* __restrict__ E, float* __restrict__ out) {
    const int row  = blockIdx.x * 8 + (threadIdx.x >> 5);
    const int lane = threadIdx.x & 31;

    float v0 = -2.f, v1 = -2.f, v2 = -2.f;
    int   i0 = 0x7fffffff, i1 = 0x7fffffff, i2 = 0x7fffffff;
    float Z = 0.f;
    #pragma unroll
    for (int s = 0; s < 4; s++) {
        const int slot = lane * 4 + s;       // ascending slots => ascending idx ranges
        float4 h0 = __ldg(&g_part[slot][row][0]);
        float4 h1 = __ldg(&g_part[slot][row][1]);
        Z += h1.z;
        ins3(v0, v1, v2, i0, i1, i2, h0.x, __float_as_int(h0.w));
        ins3(v0, v1, v2, i0, i1, i2, h0.y, __float_as_int(h1.x));
        ins3(v0, v1, v2, i0, i1, i2, h0.z, __float_as_int(h1.y));
    }
    #pragma unroll
    for (int o = 1; o < 32; o <<= 1) {
        float ov0 = __shfl_xor_sync(0xffffffffu, v0, o);
        float ov1 = __shfl_xor_sync(0xffffffffu, v1, o);
        float ov2 = __shfl_xor_sync(0xffffffffu, v2, o);
        int oi0 = __shfl_xor_sync(0xffffffffu, i0, o);
        int oi1 = __shfl_xor_sync(0xffffffffu, i1, o);
        int oi2 = __shfl_xor_sync(0xffffffffu, i2, o);
        Z += __shfl_xor_sync(0xffffffffu, Z, o);
        ins3(v0, v1, v2, i0, i1, i2, ov0, oi0);
        ins3(v0, v1, v2, i0, i1, i2, ov1, oi1);
        ins3(v0, v1, v2, i0, i1, i2, ov2, oi2);
    }

    const float s0 = __expf(v0 - 1.f) / Z;
    const float s1 = __expf(v1 - 1.f) / Z;
    const float s2 = __expf(v2 - 1.f) / Z;
    const float mx = fmaxf(s0, fmaxf(s1, s2));
    const float e0 = __expf(s0 - mx), e1 = __expf(s1 - mx), e2 = __expf(s2 - mx);
    const float inv = 1.f / (e0 + e1 + e2);
    const float w0 = e0 * inv, w1 = e1 * inv, w2 = e2 * inv;

    const float* p0 = E + (size_t)i0 * D;
    const float* p1 = E + (size_t)i1 * D;
    const float* p2 = E + (size_t)i2 * D;
    #pragma unroll
    for (int t = 0; t < 2; t++) {
        const int cc = lane * 8 + t * 4;
        float4 a = __ldg((const float4*)(p0 + cc));
        float4 b = __ldg((const float4*)(p1 + cc));
        float4 c = __ldg((const float4*)(p2 + cc));
        float4 o;
        o.x = w0 * a.x + w1 * b.x + w2 * c.x;
        o.y = w0 * a.y + w1 * b.y + w2 * c.y;
        o.z = w0 * a.z + w1 * b.z + w2 * c.z;
        o.w = w0 * a.w + w1 * b.w + w2 * c.w;
        *(float4*)(out + (size_t)row * D + cc) = o;
    }
}

// ---------------------------------------------------------------------------
extern "C" void kernel_launch(void* const* d_in, const int* in_sizes, int n_in,
                              void* d_out, int out_size) {
    const float* E = (const float*)d_in[0];
    float* out = (float*)d_out;
    const int n = in_sizes[0] / D;      // 16384
    if (n <= 0) return;

    cudaFuncSetAttribute(sym_kernel, cudaFuncAttributeMaxDynamicSharedMemorySize, DYNSMEM);

    norm_t_kernel<<<NTOT / 32, 256>>>(E);
    dim3 g1(NT, NT);
    sym_kernel<<<g1, 256, DYNSMEM>>>();
    reduce_kernel<<<NTOT / 8, 256>>>(E, out);
}